// round 1
// baseline (speedup 1.0000x reference)
#include <cuda_runtime.h>
#include <math.h>

#define B_ROWS 2048
#define D_DIM  512
#define C_CLS  32768
#define S_SCALE 64.0f
#define MARGIN  0.5f
#define EPS_CLIP 1e-7f

#define BM 128
#define BN 128
#define BK 16

// Scratch (static device globals -- no allocation allowed in kernel_launch)
__device__ float g_inv_f[B_ROWS];
__device__ float g_inv_w[C_CLS];
__device__ float g_rowsum[B_ROWS];
__device__ float g_tgt[B_ROWS];

// ---------------------------------------------------------------------------
__global__ void zero_rowsum_kernel() {
    int i = blockIdx.x * blockDim.x + threadIdx.x;
    if (i < B_ROWS) g_rowsum[i] = 0.0f;
}

// warp-per-row inverse L2 norm: inv = 1 / max(||x||, 1e-12)
__global__ void inv_norm_f_kernel(const float* __restrict__ x) {
    int warp = (blockIdx.x * blockDim.x + threadIdx.x) >> 5;
    int lane = threadIdx.x & 31;
    if (warp >= B_ROWS) return;
    const float4* p = (const float4*)(x + (size_t)warp * D_DIM);
    float ss = 0.0f;
#pragma unroll
    for (int i = 0; i < 4; i++) {
        float4 v = p[lane + 32 * i];
        ss = fmaf(v.x, v.x, fmaf(v.y, v.y, fmaf(v.z, v.z, fmaf(v.w, v.w, ss))));
    }
#pragma unroll
    for (int o = 16; o; o >>= 1) ss += __shfl_xor_sync(0xffffffffu, ss, o);
    if (lane == 0) g_inv_f[warp] = 1.0f / fmaxf(sqrtf(ss), 1e-12f);
}

__global__ void inv_norm_w_kernel(const float* __restrict__ x) {
    int warp = (blockIdx.x * blockDim.x + threadIdx.x) >> 5;
    int lane = threadIdx.x & 31;
    if (warp >= C_CLS) return;
    const float4* p = (const float4*)(x + (size_t)warp * D_DIM);
    float ss = 0.0f;
#pragma unroll
    for (int i = 0; i < 4; i++) {
        float4 v = p[lane + 32 * i];
        ss = fmaf(v.x, v.x, fmaf(v.y, v.y, fmaf(v.z, v.z, fmaf(v.w, v.w, ss))));
    }
#pragma unroll
    for (int o = 16; o; o >>= 1) ss += __shfl_xor_sync(0xffffffffu, ss, o);
    if (lane == 0) g_inv_w[warp] = 1.0f / fmaxf(sqrtf(ss), 1e-12f);
}

// warp-per-row target cosine: tgt[b] = (f[b] . w[y[b]]) * inv_f[b] * inv_w[y[b]]
__global__ void tgt_kernel(const float* __restrict__ f,
                           const int* __restrict__ y,
                           const float* __restrict__ w) {
    int warp = (blockIdx.x * blockDim.x + threadIdx.x) >> 5;
    int lane = threadIdx.x & 31;
    if (warp >= B_ROWS) return;
    int cls = y[warp];
    const float4* fp = (const float4*)(f + (size_t)warp * D_DIM);
    const float4* wp = (const float4*)(w + (size_t)cls * D_DIM);
    float dot = 0.0f;
#pragma unroll
    for (int i = 0; i < 4; i++) {
        float4 a = fp[lane + 32 * i];
        float4 b = wp[lane + 32 * i];
        dot = fmaf(a.x, b.x, fmaf(a.y, b.y, fmaf(a.z, b.z, fmaf(a.w, b.w, dot))));
    }
#pragma unroll
    for (int o = 16; o; o >>= 1) dot += __shfl_xor_sync(0xffffffffu, dot, o);
    if (lane == 0) g_tgt[warp] = dot * g_inv_f[warp] * g_inv_w[cls];
}

// ---------------------------------------------------------------------------
// Fused GEMM + exp-sum epilogue.
// acc[b, c] = features[b,:] . weight[c,:]   (raw dot; normalization at epilogue)
// epilogue: rowsum[b] += sum_c exp(S * acc * inv_f[b] * inv_w[c])
__global__ __launch_bounds__(256, 2)
void gemm_exp_kernel(const float* __restrict__ F, const float* __restrict__ W) {
    __shared__ float As[2][BK][BM];
    __shared__ float Bs[2][BK][BN];

    const int tid = threadIdx.x;
    const int tx = tid & 15;
    const int ty = tid >> 4;
    const int m0 = blockIdx.y * BM;
    const int n0 = blockIdx.x * BN;

    // loaders: 256 threads cover 128x16 tile twice (rows lrow, lrow+64), float4 in k
    const int lrow = tid >> 2;            // 0..63
    const int lcol = (tid & 3) << 2;      // 0,4,8,12

    const float* Ag0 = F + (size_t)(m0 + lrow) * D_DIM + lcol;
    const float* Ag1 = F + (size_t)(m0 + lrow + 64) * D_DIM + lcol;
    const float* Bg0 = W + (size_t)(n0 + lrow) * D_DIM + lcol;
    const float* Bg1 = W + (size_t)(n0 + lrow + 64) * D_DIM + lcol;

    float acc[8][8];
#pragma unroll
    for (int i = 0; i < 8; i++)
#pragma unroll
        for (int j = 0; j < 8; j++) acc[i][j] = 0.0f;

    // prologue: tile 0
    {
        float4 a0 = *(const float4*)Ag0;
        float4 a1 = *(const float4*)Ag1;
        float4 b0 = *(const float4*)Bg0;
        float4 b1 = *(const float4*)Bg1;
        As[0][lcol + 0][lrow] = a0.x; As[0][lcol + 1][lrow] = a0.y;
        As[0][lcol + 2][lrow] = a0.z; As[0][lcol + 3][lrow] = a0.w;
        As[0][lcol + 0][lrow + 64] = a1.x; As[0][lcol + 1][lrow + 64] = a1.y;
        As[0][lcol + 2][lrow + 64] = a1.z; As[0][lcol + 3][lrow + 64] = a1.w;
        Bs[0][lcol + 0][lrow] = b0.x; Bs[0][lcol + 1][lrow] = b0.y;
        Bs[0][lcol + 2][lrow] = b0.z; Bs[0][lcol + 3][lrow] = b0.w;
        Bs[0][lcol + 0][lrow + 64] = b1.x; Bs[0][lcol + 1][lrow + 64] = b1.y;
        Bs[0][lcol + 2][lrow + 64] = b1.z; Bs[0][lcol + 3][lrow + 64] = b1.w;
    }
    __syncthreads();

    int buf = 0;
    const int KT = D_DIM / BK; // 32
#pragma unroll 1
    for (int t = 0; t < KT; t++) {
        float4 na0, na1, nb0, nb1;
        const bool has_next = (t + 1 < KT);
        if (has_next) {
            int ko = (t + 1) * BK;
            na0 = *(const float4*)(Ag0 + ko);
            na1 = *(const float4*)(Ag1 + ko);
            nb0 = *(const float4*)(Bg0 + ko);
            nb1 = *(const float4*)(Bg1 + ko);
        }
#pragma unroll
        for (int k = 0; k < BK; k++) {
            float ra[8], rb[8];
            *(float4*)(ra)     = *(const float4*)&As[buf][k][ty * 4];
            *(float4*)(ra + 4) = *(const float4*)&As[buf][k][64 + ty * 4];
            *(float4*)(rb)     = *(const float4*)&Bs[buf][k][tx * 4];
            *(float4*)(rb + 4) = *(const float4*)&Bs[buf][k][64 + tx * 4];
#pragma unroll
            for (int i = 0; i < 8; i++)
#pragma unroll
                for (int j = 0; j < 8; j++)
                    acc[i][j] = fmaf(ra[i], rb[j], acc[i][j]);
        }
        if (has_next) {
            int nbuf = buf ^ 1;
            As[nbuf][lcol + 0][lrow] = na0.x; As[nbuf][lcol + 1][lrow] = na0.y;
            As[nbuf][lcol + 2][lrow] = na0.z; As[nbuf][lcol + 3][lrow] = na0.w;
            As[nbuf][lcol + 0][lrow + 64] = na1.x; As[nbuf][lcol + 1][lrow + 64] = na1.y;
            As[nbuf][lcol + 2][lrow + 64] = na1.z; As[nbuf][lcol + 3][lrow + 64] = na1.w;
            Bs[nbuf][lcol + 0][lrow] = nb0.x; Bs[nbuf][lcol + 1][lrow] = nb0.y;
            Bs[nbuf][lcol + 2][lrow] = nb0.z; Bs[nbuf][lcol + 3][lrow] = nb0.w;
            Bs[nbuf][lcol + 0][lrow + 64] = nb1.x; Bs[nbuf][lcol + 1][lrow + 64] = nb1.y;
            Bs[nbuf][lcol + 2][lrow + 64] = nb1.z; Bs[nbuf][lcol + 3][lrow + 64] = nb1.w;
            __syncthreads();
            buf = nbuf;
        }
    }

    // epilogue: scale -> exp -> per-row reduce across tx -> atomicAdd
    int rA[8], cB[8];
#pragma unroll
    for (int i = 0; i < 4; i++) {
        rA[i]     = m0 + ty * 4 + i;
        rA[i + 4] = m0 + 64 + ty * 4 + i;
        cB[i]     = n0 + tx * 4 + i;
        cB[i + 4] = n0 + 64 + tx * 4 + i;
    }
    float invf[8], invw[8];
#pragma unroll
    for (int i = 0; i < 8; i++) { invf[i] = g_inv_f[rA[i]]; invw[i] = g_inv_w[cB[i]]; }

    float rs[8];
#pragma unroll
    for (int i = 0; i < 8; i++) {
        float s = 0.0f;
        float fi = S_SCALE * invf[i];
#pragma unroll
        for (int j = 0; j < 8; j++) {
            float e = __expf(acc[i][j] * fi * invw[j]);
            s += e;
        }
        rs[i] = s;
    }
    // reduce across the 16 tx lanes sharing each row (warp = 2 ty groups of 16)
#pragma unroll
    for (int o = 1; o < 16; o <<= 1)
#pragma unroll
        for (int i = 0; i < 8; i++)
            rs[i] += __shfl_xor_sync(0xffffffffu, rs[i], o);
    if (tx == 0) {
#pragma unroll
        for (int i = 0; i < 8; i++) atomicAdd(&g_rowsum[rA[i]], rs[i]);
    }
}

// ---------------------------------------------------------------------------
__global__ void loss_kernel(float* __restrict__ out) {
    __shared__ double sh[256];
    double a = 0.0;
    for (int b = threadIdx.x; b < B_ROWS; b += blockDim.x) {
        float t = fminf(fmaxf(g_tgt[b], -1.0f + EPS_CLIP), 1.0f - EPS_CLIP);
        float num = S_SCALE * cosf(acosf(t) + MARGIN);
        float excl = g_rowsum[b] - __expf(S_SCALE * t);
        double denom = (double)__expf(num) + (double)excl;
        a += (double)num - log(denom);
    }
    sh[threadIdx.x] = a;
    __syncthreads();
    for (int s = 128; s > 0; s >>= 1) {
        if (threadIdx.x < s) sh[threadIdx.x] += sh[threadIdx.x + s];
        __syncthreads();
    }
    if (threadIdx.x == 0) out[0] = (float)(-sh[0] / (double)B_ROWS);
}

// ---------------------------------------------------------------------------
extern "C" void kernel_launch(void* const* d_in, const int* in_sizes, int n_in,
                              void* d_out, int out_size) {
    const float* F = (const float*)d_in[0];   // features [2048,512]
    const int*   Y = (const int*)d_in[1];     // y_true   [2048]
    const float* W = (const float*)d_in[2];   // weight   [32768,512]
    float* out = (float*)d_out;

    zero_rowsum_kernel<<<(B_ROWS + 255) / 256, 256>>>();
    inv_norm_f_kernel<<<B_ROWS / 8, 256>>>(F);
    inv_norm_w_kernel<<<C_CLS / 8, 256>>>(W);
    tgt_kernel<<<B_ROWS / 8, 256>>>(F, Y, W);

    dim3 grid(C_CLS / BN, B_ROWS / BM); // (256, 16)
    gemm_exp_kernel<<<grid, 256>>>(F, W);

    loss_kernel<<<1, 256>>>(out);
}

// round 3
// speedup vs baseline: 2.6998x; 2.6998x over previous
#include <cuda_runtime.h>
#include <math.h>
#include <stdint.h>

#define B_ROWS 2048
#define D_DIM  512
#define C_CLS  32768
#define S_SCALE 64.0f
#define MARGIN  0.5f
#define EPS_CLIP 1e-7f

#define BM 128
#define BN 128
#define NCH 16                 // 512 / 32
#define BUF_BYTES 32768        // A 16KB + B 16KB per stage
#define B_REGION  16384

// ---------------------------------------------------------------------------
__device__ float g_inv_f[B_ROWS];
__device__ float g_inv_w[C_CLS];
__device__ float g_rowsum[B_ROWS];
__device__ float g_tgt[B_ROWS];
__device__ float g_Fs[B_ROWS * D_DIM];   // S * f_hat (tf32-rounded)
__device__ float g_Ws[C_CLS * D_DIM];    // w_hat     (tf32-rounded)

__device__ __forceinline__ float to_tf32(float x) {
    float r; asm("cvt.rna.tf32.f32 %0, %1;" : "=f"(r) : "f"(x)); return r;
}

__device__ __forceinline__ void mma_tf32(float* c, const float4& a,
                                         uint32_t b0, uint32_t b1) {
    asm volatile(
        "mma.sync.aligned.m16n8k8.row.col.f32.tf32.tf32.f32 "
        "{%0,%1,%2,%3}, {%4,%5,%6,%7}, {%8,%9}, {%0,%1,%2,%3};"
        : "+f"(c[0]), "+f"(c[1]), "+f"(c[2]), "+f"(c[3])
        : "r"(__float_as_uint(a.x)), "r"(__float_as_uint(a.y)),
          "r"(__float_as_uint(a.z)), "r"(__float_as_uint(a.w)),
          "r"(b0), "r"(b1));
}

// ---------------------------------------------------------------------------
__global__ void zero_rowsum_kernel() {
    int i = blockIdx.x * blockDim.x + threadIdx.x;
    if (i < B_ROWS) g_rowsum[i] = 0.0f;
}

__global__ void norm_scale_f_kernel(const float* __restrict__ x) {
    int warp = (blockIdx.x * blockDim.x + threadIdx.x) >> 5;
    int lane = threadIdx.x & 31;
    if (warp >= B_ROWS) return;
    const float4* p = (const float4*)(x + (size_t)warp * D_DIM);
    float4 v[4]; float ss = 0.0f;
#pragma unroll
    for (int i = 0; i < 4; i++) {
        v[i] = p[lane + 32 * i];
        ss = fmaf(v[i].x, v[i].x, fmaf(v[i].y, v[i].y, fmaf(v[i].z, v[i].z, fmaf(v[i].w, v[i].w, ss))));
    }
#pragma unroll
    for (int o = 16; o; o >>= 1) ss += __shfl_xor_sync(0xffffffffu, ss, o);
    float inv = 1.0f / fmaxf(sqrtf(ss), 1e-12f);
    if (lane == 0) g_inv_f[warp] = inv;
    float sc = inv * S_SCALE;
    float4* out = (float4*)(g_Fs + (size_t)warp * D_DIM);
#pragma unroll
    for (int i = 0; i < 4; i++) {
        float4 o4;
        o4.x = to_tf32(v[i].x * sc); o4.y = to_tf32(v[i].y * sc);
        o4.z = to_tf32(v[i].z * sc); o4.w = to_tf32(v[i].w * sc);
        out[lane + 32 * i] = o4;
    }
}

__global__ void norm_scale_w_kernel(const float* __restrict__ x) {
    int warp = (blockIdx.x * blockDim.x + threadIdx.x) >> 5;
    int lane = threadIdx.x & 31;
    if (warp >= C_CLS) return;
    const float4* p = (const float4*)(x + (size_t)warp * D_DIM);
    float4 v[4]; float ss = 0.0f;
#pragma unroll
    for (int i = 0; i < 4; i++) {
        v[i] = p[lane + 32 * i];
        ss = fmaf(v[i].x, v[i].x, fmaf(v[i].y, v[i].y, fmaf(v[i].z, v[i].z, fmaf(v[i].w, v[i].w, ss))));
    }
#pragma unroll
    for (int o = 16; o; o >>= 1) ss += __shfl_xor_sync(0xffffffffu, ss, o);
    float inv = 1.0f / fmaxf(sqrtf(ss), 1e-12f);
    if (lane == 0) g_inv_w[warp] = inv;
    float4* out = (float4*)(g_Ws + (size_t)warp * D_DIM);
#pragma unroll
    for (int i = 0; i < 4; i++) {
        float4 o4;
        o4.x = to_tf32(v[i].x * inv); o4.y = to_tf32(v[i].y * inv);
        o4.z = to_tf32(v[i].z * inv); o4.w = to_tf32(v[i].w * inv);
        out[lane + 32 * i] = o4;
    }
}

__global__ void tgt_kernel(const float* __restrict__ f,
                           const int* __restrict__ y,
                           const float* __restrict__ w) {
    int warp = (blockIdx.x * blockDim.x + threadIdx.x) >> 5;
    int lane = threadIdx.x & 31;
    if (warp >= B_ROWS) return;
    int cls = y[warp];
    const float4* fp = (const float4*)(f + (size_t)warp * D_DIM);
    const float4* wp = (const float4*)(w + (size_t)cls * D_DIM);
    float dot = 0.0f;
#pragma unroll
    for (int i = 0; i < 4; i++) {
        float4 a = fp[lane + 32 * i];
        float4 b = wp[lane + 32 * i];
        dot = fmaf(a.x, b.x, fmaf(a.y, b.y, fmaf(a.z, b.z, fmaf(a.w, b.w, dot))));
    }
#pragma unroll
    for (int o = 16; o; o >>= 1) dot += __shfl_xor_sync(0xffffffffu, dot, o);
    if (lane == 0) g_tgt[warp] = dot * g_inv_f[warp] * g_inv_w[cls];
}

// ---------------------------------------------------------------------------
// tf32 mma.sync GEMM, 128x128 tile, K=512 in 16 chunks of 32, double-buffered.
// Epilogue: exp(acc) -> per-row sum -> atomicAdd into g_rowsum.
__global__ void __launch_bounds__(256, 1)
gemm_exp_mma_kernel() {
    extern __shared__ __align__(16) char smb[];   // 2 * 32KB
    const int tid  = threadIdx.x;
    const int lane = tid & 31;
    const int warp = tid >> 5;
    const int wm = warp >> 2;          // 0..1
    const int wn = warp & 3;           // 0..3
    const int tm = blockIdx.y;
    const int tn = blockIdx.x;

    // ---- per-thread loader setup: 4 float4 of A, 4 of B per chunk ----
    const float* gA[4];
    const float* gB[4];
    uint32_t stA[4], stB[4];           // smem byte offsets (element e=0)
#pragma unroll
    for (int i = 0; i < 4; i++) {
        int idx = tid + i * 256;       // 0..1023
        int row = idx >> 3;            // 0..127
        int j   = idx & 7;             // float4 index in k (k = j*4..j*4+3)
        gA[i] = g_Fs + (size_t)(tm * BM + row) * D_DIM + j * 4;
        gB[i] = g_Ws + (size_t)(tn * BN + row) * D_DIM + j * 4;
        int ks = j >> 1;
        int khi = (j & 1) << 1;        // kk>>2 for e=0..3 (kk = (j&1)*4 + e)
        // A scatter base (e = 0)
        {
            int wmw = row >> 6, mm = row & 63, mt = mm >> 4, r = mm & 15;
            int ln = (r & 7) << 2;
            ln ^= ((ln >> 3) & 3) << 1;
            ln ^= (ks & 1);
            int slot = khi | (r >> 3);
            stA[i] = (uint32_t)(((((ks * 2 + wmw) * 4 + mt) * 32 + ln) << 4) + (slot << 2));
        }
        // B scatter base (e = 0)
        {
            int wnw = row >> 5, nn = row & 31, nt = nn >> 3, g = nn & 7;
            int ln = g << 2;
            ln ^= ((ln >> 3) & 3) << 1;
            ln ^= (ks & 1);
            int slot = ((nt & 1) << 1) | (khi >> 1);
            stB[i] = (uint32_t)(B_REGION + ((((ks * 4 + wnw) * 2 + (nt >> 1)) * 32 + ln) << 4) + (slot << 2));
        }
    }

    const int lxs = lane ^ (((lane >> 3) & 3) << 1);  // read-side swizzle base

    float acc[4][4][4];
#pragma unroll
    for (int a = 0; a < 4; a++)
#pragma unroll
        for (int b = 0; b < 4; b++)
#pragma unroll
            for (int c = 0; c < 4; c++) acc[a][b][c] = 0.0f;

    float4 vA[4], vB[4];

    // prologue: chunk 0
#pragma unroll
    for (int i = 0; i < 4; i++) { vA[i] = *(const float4*)(gA[i]); vB[i] = *(const float4*)(gB[i]); }
    {
        char* buf = smb;
#pragma unroll
        for (int i = 0; i < 4; i++) {
            *(float*)(buf + (stA[i] ^ 0 ))  = vA[i].x;
            *(float*)(buf + (stA[i] ^ 16))  = vA[i].y;
            *(float*)(buf + (stA[i] ^ 32))  = vA[i].z;
            *(float*)(buf + (stA[i] ^ 48))  = vA[i].w;
            *(float*)(buf + (stB[i] ^ 0 ))  = vB[i].x;
            *(float*)(buf + (stB[i] ^ 16))  = vB[i].y;
            *(float*)(buf + (stB[i] ^ 32))  = vB[i].z;
            *(float*)(buf + (stB[i] ^ 48))  = vB[i].w;
        }
    }
    __syncthreads();

#pragma unroll 1
    for (int c = 0; c < NCH; c++) {
        if (c + 1 < NCH) {
            const int ko = (c + 1) * 32;
#pragma unroll
            for (int i = 0; i < 4; i++) {
                vA[i] = *(const float4*)(gA[i] + ko);
                vB[i] = *(const float4*)(gB[i] + ko);
            }
        }
        const char* buf = smb + (c & 1) * BUF_BYTES;
#pragma unroll
        for (int ks = 0; ks < 4; ks++) {
            const int lr = lxs ^ (ks & 1);
            float4 afr[4], bfr[2];
#pragma unroll
            for (int mt = 0; mt < 4; mt++)
                afr[mt] = *(const float4*)(buf + (((((ks * 2 + wm) * 4 + mt) * 32) + lr) << 4));
#pragma unroll
            for (int np = 0; np < 2; np++)
                bfr[np] = *(const float4*)(buf + B_REGION + (((((ks * 4 + wn) * 2 + np) * 32) + lr) << 4));
#pragma unroll
            for (int mt = 0; mt < 4; mt++) {
                mma_tf32(acc[mt][0], afr[mt], __float_as_uint(bfr[0].x), __float_as_uint(bfr[0].y));
                mma_tf32(acc[mt][1], afr[mt], __float_as_uint(bfr[0].z), __float_as_uint(bfr[0].w));
                mma_tf32(acc[mt][2], afr[mt], __float_as_uint(bfr[1].x), __float_as_uint(bfr[1].y));
                mma_tf32(acc[mt][3], afr[mt], __float_as_uint(bfr[1].z), __float_as_uint(bfr[1].w));
            }
        }
        if (c + 1 < NCH) {
            char* nbuf = smb + ((c + 1) & 1) * BUF_BYTES;
#pragma unroll
            for (int i = 0; i < 4; i++) {
                *(float*)(nbuf + (stA[i] ^ 0 )) = vA[i].x;
                *(float*)(nbuf + (stA[i] ^ 16)) = vA[i].y;
                *(float*)(nbuf + (stA[i] ^ 32)) = vA[i].z;
                *(float*)(nbuf + (stA[i] ^ 48)) = vA[i].w;
                *(float*)(nbuf + (stB[i] ^ 0 )) = vB[i].x;
                *(float*)(nbuf + (stB[i] ^ 16)) = vB[i].y;
                *(float*)(nbuf + (stB[i] ^ 32)) = vB[i].z;
                *(float*)(nbuf + (stB[i] ^ 48)) = vB[i].w;
            }
        }
        __syncthreads();
    }

    // ---- epilogue: exp + row reduce + atomicAdd ----
    float s[4][2];
#pragma unroll
    for (int mt = 0; mt < 4; mt++) {
        float s0 = 0.0f, s1 = 0.0f;
#pragma unroll
        for (int nt = 0; nt < 4; nt++) {
            s0 += __expf(acc[mt][nt][0]) + __expf(acc[mt][nt][1]);
            s1 += __expf(acc[mt][nt][2]) + __expf(acc[mt][nt][3]);
        }
        s[mt][0] = s0; s[mt][1] = s1;
    }
#pragma unroll
    for (int o = 1; o < 4; o <<= 1)
#pragma unroll
        for (int mt = 0; mt < 4; mt++) {
            s[mt][0] += __shfl_xor_sync(0xffffffffu, s[mt][0], o);
            s[mt][1] += __shfl_xor_sync(0xffffffffu, s[mt][1], o);
        }
    if ((lane & 3) == 0) {
        int g = lane >> 2;
        int base = tm * BM + wm * 64 + g;
#pragma unroll
        for (int mt = 0; mt < 4; mt++) {
            atomicAdd(&g_rowsum[base + mt * 16],     s[mt][0]);
            atomicAdd(&g_rowsum[base + mt * 16 + 8], s[mt][1]);
        }
    }
}

// ---------------------------------------------------------------------------
__global__ void loss_kernel(float* __restrict__ out) {
    __shared__ double sh[256];
    double a = 0.0;
    for (int b = threadIdx.x; b < B_ROWS; b += blockDim.x) {
        float t = fminf(fmaxf(g_tgt[b], -1.0f + EPS_CLIP), 1.0f - EPS_CLIP);
        float num = S_SCALE * cosf(acosf(t) + MARGIN);
        float excl = g_rowsum[b] - __expf(S_SCALE * t);
        double denom = (double)__expf(num) + (double)excl;
        a += (double)num - log(denom);
    }
    sh[threadIdx.x] = a;
    __syncthreads();
    for (int s = 128; s > 0; s >>= 1) {
        if (threadIdx.x < s) sh[threadIdx.x] += sh[threadIdx.x + s];
        __syncthreads();
    }
    if (threadIdx.x == 0) out[0] = (float)(-sh[0] / (double)B_ROWS);
}

// ---------------------------------------------------------------------------
extern "C" void kernel_launch(void* const* d_in, const int* in_sizes, int n_in,
                              void* d_out, int out_size) {
    const float* F = (const float*)d_in[0];
    const int*   Y = (const int*)d_in[1];
    const float* W = (const float*)d_in[2];
    float* out = (float*)d_out;

    static int smem_set = 0;
    if (!smem_set) {
        cudaFuncSetAttribute(gemm_exp_mma_kernel,
                             cudaFuncAttributeMaxDynamicSharedMemorySize, 2 * BUF_BYTES);
        smem_set = 1;
    }

    zero_rowsum_kernel<<<(B_ROWS + 255) / 256, 256>>>();
    norm_scale_f_kernel<<<B_ROWS / 8, 256>>>(F);
    norm_scale_w_kernel<<<C_CLS / 8, 256>>>(W);
    tgt_kernel<<<B_ROWS / 8, 256>>>(F, Y, W);

    dim3 grid(C_CLS / BN, B_ROWS / BM);   // (256, 16)
    gemm_exp_mma_kernel<<<grid, 256, 2 * BUF_BYTES>>>();

    loss_kernel<<<1, 256>>>(out);
}

// round 5
// speedup vs baseline: 4.5805x; 1.6966x over previous
#include <cuda_runtime.h>
#include <cuda_fp16.h>
#include <math.h>
#include <stdint.h>

#define B_ROWS 2048
#define D_DIM  512
#define C_CLS  32768
#define S_SCALE 64.0f
#define MARGIN  0.5f
#define EPS_CLIP 1e-7f

#define BM 128
#define BN 128
#define NCH 8                  // 512 / 64
#define BUF_BYTES 32768        // A 16KB + B 16KB per stage (half precision, k64)
#define B_REGION  16384

// ---------------------------------------------------------------------------
__device__ float  g_inv_f[B_ROWS];
__device__ float  g_inv_w[C_CLS];
__device__ float  g_rowsum[B_ROWS];
__device__ float  g_tgt[B_ROWS];
__device__ __align__(16) __half g_Fh[B_ROWS * D_DIM];   // S * f_hat  (fp16 rn)
__device__ __align__(16) __half g_Wh[C_CLS * D_DIM];    // w_hat      (fp16 rn)

__device__ __forceinline__ void mma_f16(float* c, const uint4& a,
                                        uint32_t b0, uint32_t b1) {
    asm volatile(
        "mma.sync.aligned.m16n8k16.row.col.f32.f16.f16.f32 "
        "{%0,%1,%2,%3}, {%4,%5,%6,%7}, {%8,%9}, {%0,%1,%2,%3};"
        : "+f"(c[0]), "+f"(c[1]), "+f"(c[2]), "+f"(c[3])
        : "r"(a.x), "r"(a.y), "r"(a.z), "r"(a.w), "r"(b0), "r"(b1));
}

__device__ __forceinline__ uint32_t pack_h2(float lo, float hi) {
    __half2 h = __floats2half2_rn(lo, hi);
    return *(uint32_t*)&h;
}

// ---------------------------------------------------------------------------
__global__ void zero_rowsum_kernel() {
    int i = blockIdx.x * blockDim.x + threadIdx.x;
    if (i < B_ROWS) g_rowsum[i] = 0.0f;
}

// warp-per-row: inv norm + fp16(S * f_hat)
__global__ void norm_scale_f_kernel(const float* __restrict__ x) {
    int warp = (blockIdx.x * blockDim.x + threadIdx.x) >> 5;
    int lane = threadIdx.x & 31;
    if (warp >= B_ROWS) return;
    const float4* p = (const float4*)(x + (size_t)warp * D_DIM);
    float4 v[4]; float ss = 0.0f;
#pragma unroll
    for (int i = 0; i < 4; i++) {
        v[i] = p[lane + 32 * i];
        ss = fmaf(v[i].x, v[i].x, fmaf(v[i].y, v[i].y, fmaf(v[i].z, v[i].z, fmaf(v[i].w, v[i].w, ss))));
    }
#pragma unroll
    for (int o = 16; o; o >>= 1) ss += __shfl_xor_sync(0xffffffffu, ss, o);
    float inv = 1.0f / fmaxf(sqrtf(ss), 1e-12f);
    if (lane == 0) g_inv_f[warp] = inv;
    float sc = inv * S_SCALE;
    uint2* out = (uint2*)(g_Fh + (size_t)warp * D_DIM);
#pragma unroll
    for (int i = 0; i < 4; i++) {
        uint2 o2;
        o2.x = pack_h2(v[i].x * sc, v[i].y * sc);
        o2.y = pack_h2(v[i].z * sc, v[i].w * sc);
        out[lane + 32 * i] = o2;
    }
}

__global__ void norm_scale_w_kernel(const float* __restrict__ x) {
    int warp = (blockIdx.x * blockDim.x + threadIdx.x) >> 5;
    int lane = threadIdx.x & 31;
    if (warp >= C_CLS) return;
    const float4* p = (const float4*)(x + (size_t)warp * D_DIM);
    float4 v[4]; float ss = 0.0f;
#pragma unroll
    for (int i = 0; i < 4; i++) {
        v[i] = p[lane + 32 * i];
        ss = fmaf(v[i].x, v[i].x, fmaf(v[i].y, v[i].y, fmaf(v[i].z, v[i].z, fmaf(v[i].w, v[i].w, ss))));
    }
#pragma unroll
    for (int o = 16; o; o >>= 1) ss += __shfl_xor_sync(0xffffffffu, ss, o);
    float inv = 1.0f / fmaxf(sqrtf(ss), 1e-12f);
    if (lane == 0) g_inv_w[warp] = inv;
    uint2* out = (uint2*)(g_Wh + (size_t)warp * D_DIM);
#pragma unroll
    for (int i = 0; i < 4; i++) {
        uint2 o2;
        o2.x = pack_h2(v[i].x * inv, v[i].y * inv);
        o2.y = pack_h2(v[i].z * inv, v[i].w * inv);
        out[lane + 32 * i] = o2;
    }
}

// exact fp32 target cosine (reads original fp32 inputs)
__global__ void tgt_kernel(const float* __restrict__ f,
                           const int* __restrict__ y,
                           const float* __restrict__ w) {
    int warp = (blockIdx.x * blockDim.x + threadIdx.x) >> 5;
    int lane = threadIdx.x & 31;
    if (warp >= B_ROWS) return;
    int cls = y[warp];
    const float4* fp = (const float4*)(f + (size_t)warp * D_DIM);
    const float4* wp = (const float4*)(w + (size_t)cls * D_DIM);
    float dot = 0.0f;
#pragma unroll
    for (int i = 0; i < 4; i++) {
        float4 a = fp[lane + 32 * i];
        float4 b = wp[lane + 32 * i];
        dot = fmaf(a.x, b.x, fmaf(a.y, b.y, fmaf(a.z, b.z, fmaf(a.w, b.w, dot))));
    }
#pragma unroll
    for (int o = 16; o; o >>= 1) dot += __shfl_xor_sync(0xffffffffu, dot, o);
    if (lane == 0) g_tgt[warp] = dot * g_inv_f[warp] * g_inv_w[cls];
}

// ---------------------------------------------------------------------------
// fp16 mma.sync m16n8k16 GEMM, 128x128 tile, K=512 in 8 chunks of 64,
// double-buffered smem with fragment-ordered scatter stores.
// acc = logit = 64 * cos. Epilogue: exp -> per-row sum -> atomicAdd.
__global__ void __launch_bounds__(256, 1)
gemm_exp_mma_kernel() {
    extern __shared__ __align__(16) char smb[];   // 2 * 32KB
    const int tid  = threadIdx.x;
    const int lane = tid & 31;
    const int warp = tid >> 5;
    const int wm = warp >> 2;          // 0..1   (m half)
    const int wn = warp & 3;           // 0..3   (n quarter)
    const int tm = blockIdx.y;
    const int tn = blockIdx.x;

    // ---- loader setup: per thread 4 LDG.128 of A + 4 of B per k64 chunk ----
    const __half* gA[4];
    const __half* gB[4];
    uint32_t stA[4], stB[4];   // smem byte offset of the component-0 slot
#pragma unroll
    for (int i = 0; i < 4; i++) {
        int idx = tid + i * 256;        // 0..1023
        int row = idx >> 3;             // 0..127
        int j   = idx & 7;              // 8-half group in k64: k = j*8..j*8+7
        gA[i] = g_Fh + (size_t)(tm * BM + row) * D_DIM + j * 8;
        gB[i] = g_Wh + (size_t)(tn * BN + row) * D_DIM + j * 8;
        int ks  = j >> 1;               // k16 step 0..3
        int khi = j & 1;                // high k8 within the k16 step
        // A scatter base (component 0 -> consumer lane L = r0*4)
        {
            int mm = row & 63, wmw = row >> 6, mt = mm >> 4, r = mm & 15;
            int r0 = r & 7, rbit = r >> 3;
            int L = r0 << 2;
            int phys = L ^ (((L >> 3) & 3) << 1) ^ (ks & 1);
            int region = (ks * 2 + wmw) * 4 + mt;       // 0..31
            stA[i] = (uint32_t)(region * 512 + phys * 16 + khi * 8 + rbit * 4);
        }
        // B scatter base (component 0 -> consumer lane L = g*4)
        {
            int nn = row & 31, wnw = row >> 5, nt = nn >> 3, g = nn & 7;
            int np = nt >> 1, nb = nt & 1;
            int L = g << 2;
            int phys = L ^ (((L >> 3) & 3) << 1) ^ (ks & 1);
            int region = (ks * 4 + wnw) * 2 + np;       // 0..31
            stB[i] = (uint32_t)(B_REGION + region * 512 + phys * 16 + nb * 8 + khi * 4);
        }
    }

    const int lxs = lane ^ (((lane >> 3) & 3) << 1);

    float acc[4][4][4];
#pragma unroll
    for (int a = 0; a < 4; a++)
#pragma unroll
        for (int b = 0; b < 4; b++)
#pragma unroll
            for (int c = 0; c < 4; c++) acc[a][b][c] = 0.0f;

    uint4 vA[4], vB[4];

    // prologue: chunk 0
#pragma unroll
    for (int i = 0; i < 4; i++) {
        vA[i] = *(const uint4*)(gA[i]);
        vB[i] = *(const uint4*)(gB[i]);
    }
    {
        char* buf = smb;
#pragma unroll
        for (int i = 0; i < 4; i++) {
            // XOR scatter: toggles lane bits (addr bits 4..5) under the swizzle
            *(uint32_t*)(buf + (stA[i] ^ 0 )) = vA[i].x;
            *(uint32_t*)(buf + (stA[i] ^ 16)) = vA[i].y;
            *(uint32_t*)(buf + (stA[i] ^ 32)) = vA[i].z;
            *(uint32_t*)(buf + (stA[i] ^ 48)) = vA[i].w;
            *(uint32_t*)(buf + (stB[i] ^ 0 )) = vB[i].x;
            *(uint32_t*)(buf + (stB[i] ^ 16)) = vB[i].y;
            *(uint32_t*)(buf + (stB[i] ^ 32)) = vB[i].z;
            *(uint32_t*)(buf + (stB[i] ^ 48)) = vB[i].w;
        }
    }
    __syncthreads();

#pragma unroll 1
    for (int c = 0; c < NCH; c++) {
        if (c + 1 < NCH) {
            const int ko = (c + 1) * 64;
#pragma unroll
            for (int i = 0; i < 4; i++) {
                vA[i] = *(const uint4*)(gA[i] + ko);
                vB[i] = *(const uint4*)(gB[i] + ko);
            }
        }
        const char* buf = smb + (c & 1) * BUF_BYTES;
#pragma unroll
        for (int ks = 0; ks < 4; ks++) {
            const int lr = lxs ^ (ks & 1);
            uint4 afr[4], bfr[2];
#pragma unroll
            for (int mt = 0; mt < 4; mt++)
                afr[mt] = *(const uint4*)(buf + (((ks * 2 + wm) * 4 + mt) * 32 + lr) * 16);
#pragma unroll
            for (int np = 0; np < 2; np++)
                bfr[np] = *(const uint4*)(buf + B_REGION + (((ks * 4 + wn) * 2 + np) * 32 + lr) * 16);
#pragma unroll
            for (int mt = 0; mt < 4; mt++) {
                mma_f16(acc[mt][0], afr[mt], bfr[0].x, bfr[0].y);
                mma_f16(acc[mt][1], afr[mt], bfr[0].z, bfr[0].w);
                mma_f16(acc[mt][2], afr[mt], bfr[1].x, bfr[1].y);
                mma_f16(acc[mt][3], afr[mt], bfr[1].z, bfr[1].w);
            }
        }
        if (c + 1 < NCH) {
            char* nbuf = smb + ((c + 1) & 1) * BUF_BYTES;
#pragma unroll
            for (int i = 0; i < 4; i++) {
                *(uint32_t*)(nbuf + (stA[i] ^ 0 )) = vA[i].x;
                *(uint32_t*)(nbuf + (stA[i] ^ 16)) = vA[i].y;
                *(uint32_t*)(nbuf + (stA[i] ^ 32)) = vA[i].z;
                *(uint32_t*)(nbuf + (stA[i] ^ 48)) = vA[i].w;
                *(uint32_t*)(nbuf + (stB[i] ^ 0 )) = vB[i].x;
                *(uint32_t*)(nbuf + (stB[i] ^ 16)) = vB[i].y;
                *(uint32_t*)(nbuf + (stB[i] ^ 32)) = vB[i].z;
                *(uint32_t*)(nbuf + (stB[i] ^ 48)) = vB[i].w;
            }
        }
        __syncthreads();
    }

    // ---- epilogue: exp + row reduce + atomicAdd ----
    float s[4][2];
#pragma unroll
    for (int mt = 0; mt < 4; mt++) {
        float s0 = 0.0f, s1 = 0.0f;
#pragma unroll
        for (int nt = 0; nt < 4; nt++) {
            s0 += __expf(acc[mt][nt][0]) + __expf(acc[mt][nt][1]);
            s1 += __expf(acc[mt][nt][2]) + __expf(acc[mt][nt][3]);
        }
        s[mt][0] = s0; s[mt][1] = s1;
    }
#pragma unroll
    for (int o = 1; o < 4; o <<= 1)
#pragma unroll
        for (int mt = 0; mt < 4; mt++) {
            s[mt][0] += __shfl_xor_sync(0xffffffffu, s[mt][0], o);
            s[mt][1] += __shfl_xor_sync(0xffffffffu, s[mt][1], o);
        }
    if ((lane & 3) == 0) {
        int g = lane >> 2;
        int base = tm * BM + wm * 64 + g;
#pragma unroll
        for (int mt = 0; mt < 4; mt++) {
            atomicAdd(&g_rowsum[base + mt * 16],     s[mt][0]);
            atomicAdd(&g_rowsum[base + mt * 16 + 8], s[mt][1]);
        }
    }
}

// ---------------------------------------------------------------------------
__global__ void loss_kernel(float* __restrict__ out) {
    __shared__ double sh[256];
    double a = 0.0;
    for (int b = threadIdx.x; b < B_ROWS; b += blockDim.x) {
        float t = fminf(fmaxf(g_tgt[b], -1.0f + EPS_CLIP), 1.0f - EPS_CLIP);
        float num = S_SCALE * cosf(acosf(t) + MARGIN);
        float excl = g_rowsum[b] - __expf(S_SCALE * t);
        double denom = (double)__expf(num) + (double)excl;
        a += (double)num - log(denom);
    }
    sh[threadIdx.x] = a;
    __syncthreads();
    for (int s = 128; s > 0; s >>= 1) {
        if (threadIdx.x < s) sh[threadIdx.x] += sh[threadIdx.x + s];
        __syncthreads();
    }
    if (threadIdx.x == 0) out[0] = (float)(-sh[0] / (double)B_ROWS);
}

// ---------------------------------------------------------------------------
extern "C" void kernel_launch(void* const* d_in, const int* in_sizes, int n_in,
                              void* d_out, int out_size) {
    const float* F = (const float*)d_in[0];
    const int*   Y = (const int*)d_in[1];
    const float* W = (const float*)d_in[2];
    float* out = (float*)d_out;

    static int smem_set = 0;
    if (!smem_set) {
        cudaFuncSetAttribute(gemm_exp_mma_kernel,
                             cudaFuncAttributeMaxDynamicSharedMemorySize, 2 * BUF_BYTES);
        smem_set = 1;
    }

    zero_rowsum_kernel<<<(B_ROWS + 255) / 256, 256>>>();
    norm_scale_f_kernel<<<B_ROWS / 8, 256>>>(F);
    norm_scale_w_kernel<<<C_CLS / 8, 256>>>(W);
    tgt_kernel<<<B_ROWS / 8, 256>>>(F, Y, W);

    dim3 grid(C_CLS / BN, B_ROWS / BM);   // (256, 16)
    gemm_exp_mma_kernel<<<grid, 256, 2 * BUF_BYTES>>>();

    loss_kernel<<<1, 256>>>(out);
}

// round 6
// speedup vs baseline: 4.7566x; 1.0385x over previous
#include <cuda_runtime.h>
#include <cuda_fp16.h>
#include <math.h>
#include <stdint.h>

#define B_ROWS 2048
#define D_DIM  512
#define C_CLS  32768
#define S_SCALE 64.0f
#define MARGIN  0.5f
#define EPS_CLIP 1e-7f

#define BM 128
#define BN 128
#define NCH 8                  // 512 / 64
#define BUF_BYTES 32768        // A 16KB + B 16KB per stage (half precision, k64)
#define B_REGION  16384

// prep grid split (8 warps = 8 rows per block)
#define PREP_W_BLOCKS  (C_CLS / 8)             // 4096
#define PREP_F_BLOCKS  (B_ROWS / 8)            // 256
#define PREP_T_BLOCKS  (B_ROWS / 8)            // 256
#define PREP_BLOCKS    (PREP_W_BLOCKS + PREP_F_BLOCKS + PREP_T_BLOCKS)

// ---------------------------------------------------------------------------
__device__ float  g_rowsum[B_ROWS];
__device__ float  g_tgt[B_ROWS];
__device__ __align__(16) __half g_Fh[B_ROWS * D_DIM];   // S * f_hat  (fp16 rn)
__device__ __align__(16) __half g_Wh[C_CLS * D_DIM];    // w_hat      (fp16 rn)

__device__ __forceinline__ void mma_f16(float* c, const uint4& a,
                                        uint32_t b0, uint32_t b1) {
    asm volatile(
        "mma.sync.aligned.m16n8k16.row.col.f32.f16.f16.f32 "
        "{%0,%1,%2,%3}, {%4,%5,%6,%7}, {%8,%9}, {%0,%1,%2,%3};"
        : "+f"(c[0]), "+f"(c[1]), "+f"(c[2]), "+f"(c[3])
        : "r"(a.x), "r"(a.y), "r"(a.z), "r"(a.w), "r"(b0), "r"(b1));
}

__device__ __forceinline__ uint32_t pack_h2(float lo, float hi) {
    __half2 h = __floats2half2_rn(lo, hi);
    return *(uint32_t*)&h;
}

// ---------------------------------------------------------------------------
// Fused prep:
//   blocks [0, 4096)            : W rows -> g_Wh = fp16(w_hat)
//   blocks [4096, 4352)         : F rows -> g_Fh = fp16(S * f_hat), zero g_rowsum
//   blocks [4352, 4608)         : target cosine (self-contained: 3 dots in one pass)
__global__ void prep_kernel(const float* __restrict__ F,
                            const int* __restrict__ Y,
                            const float* __restrict__ W) {
    const int bid  = blockIdx.x;
    const int warp = threadIdx.x >> 5;
    const int lane = threadIdx.x & 31;

    if (bid < PREP_W_BLOCKS) {
        int row = bid * 8 + warp;
        const float4* p = (const float4*)(W + (size_t)row * D_DIM);
        float4 v[4]; float ss = 0.0f;
#pragma unroll
        for (int i = 0; i < 4; i++) {
            v[i] = p[lane + 32 * i];
            ss = fmaf(v[i].x, v[i].x, fmaf(v[i].y, v[i].y, fmaf(v[i].z, v[i].z, fmaf(v[i].w, v[i].w, ss))));
        }
#pragma unroll
        for (int o = 16; o; o >>= 1) ss += __shfl_xor_sync(0xffffffffu, ss, o);
        float inv = 1.0f / fmaxf(sqrtf(ss), 1e-12f);
        uint2* out = (uint2*)(g_Wh + (size_t)row * D_DIM);
#pragma unroll
        for (int i = 0; i < 4; i++) {
            uint2 o2;
            o2.x = pack_h2(v[i].x * inv, v[i].y * inv);
            o2.y = pack_h2(v[i].z * inv, v[i].w * inv);
            out[lane + 32 * i] = o2;
        }
    } else if (bid < PREP_W_BLOCKS + PREP_F_BLOCKS) {
        int row = (bid - PREP_W_BLOCKS) * 8 + warp;
        if (lane == 0) g_rowsum[row] = 0.0f;
        const float4* p = (const float4*)(F + (size_t)row * D_DIM);
        float4 v[4]; float ss = 0.0f;
#pragma unroll
        for (int i = 0; i < 4; i++) {
            v[i] = p[lane + 32 * i];
            ss = fmaf(v[i].x, v[i].x, fmaf(v[i].y, v[i].y, fmaf(v[i].z, v[i].z, fmaf(v[i].w, v[i].w, ss))));
        }
#pragma unroll
        for (int o = 16; o; o >>= 1) ss += __shfl_xor_sync(0xffffffffu, ss, o);
        float sc = S_SCALE / fmaxf(sqrtf(ss), 1e-12f);
        uint2* out = (uint2*)(g_Fh + (size_t)row * D_DIM);
#pragma unroll
        for (int i = 0; i < 4; i++) {
            uint2 o2;
            o2.x = pack_h2(v[i].x * sc, v[i].y * sc);
            o2.y = pack_h2(v[i].z * sc, v[i].w * sc);
            out[lane + 32 * i] = o2;
        }
    } else {
        int row = (bid - PREP_W_BLOCKS - PREP_F_BLOCKS) * 8 + warp;
        int cls = Y[row];
        const float4* fp = (const float4*)(F + (size_t)row * D_DIM);
        const float4* wp = (const float4*)(W + (size_t)cls * D_DIM);
        float dot = 0.0f, ff = 0.0f, ww = 0.0f;
#pragma unroll
        for (int i = 0; i < 4; i++) {
            float4 a = fp[lane + 32 * i];
            float4 b = wp[lane + 32 * i];
            dot = fmaf(a.x, b.x, fmaf(a.y, b.y, fmaf(a.z, b.z, fmaf(a.w, b.w, dot))));
            ff  = fmaf(a.x, a.x, fmaf(a.y, a.y, fmaf(a.z, a.z, fmaf(a.w, a.w, ff))));
            ww  = fmaf(b.x, b.x, fmaf(b.y, b.y, fmaf(b.z, b.z, fmaf(b.w, b.w, ww))));
        }
#pragma unroll
        for (int o = 16; o; o >>= 1) {
            dot += __shfl_xor_sync(0xffffffffu, dot, o);
            ff  += __shfl_xor_sync(0xffffffffu, ff,  o);
            ww  += __shfl_xor_sync(0xffffffffu, ww,  o);
        }
        if (lane == 0)
            g_tgt[row] = dot / (fmaxf(sqrtf(ff), 1e-12f) * fmaxf(sqrtf(ww), 1e-12f));
    }
}

// ---------------------------------------------------------------------------
// fp16 mma.sync m16n8k16 GEMM, 128x128 tile, K=512 in 8 chunks of 64,
// double-buffered smem with fragment-ordered scatter stores.
// acc = logit = 64 * cos. Epilogue: exp -> per-row sum -> atomicAdd.
__global__ void __launch_bounds__(256, 1)
gemm_exp_mma_kernel() {
    extern __shared__ __align__(16) char smb[];   // 2 * 32KB
    const int tid  = threadIdx.x;
    const int lane = tid & 31;
    const int warp = tid >> 5;
    const int wm = warp >> 2;          // 0..1   (m half)
    const int wn = warp & 3;           // 0..3   (n quarter)
    const int tm = blockIdx.y;
    const int tn = blockIdx.x;

    // ---- loader setup: per thread 4 LDG.128 of A + 4 of B per k64 chunk ----
    const __half* gA[4];
    const __half* gB[4];
    uint32_t stA[4], stB[4];   // smem byte offset of the component-0 slot
#pragma unroll
    for (int i = 0; i < 4; i++) {
        int idx = tid + i * 256;        // 0..1023
        int row = idx >> 3;             // 0..127
        int j   = idx & 7;              // 8-half group in k64: k = j*8..j*8+7
        gA[i] = g_Fh + (size_t)(tm * BM + row) * D_DIM + j * 8;
        gB[i] = g_Wh + (size_t)(tn * BN + row) * D_DIM + j * 8;
        int ks  = j >> 1;               // k16 step 0..3
        int khi = j & 1;                // high k8 within the k16 step
        // A scatter base (component 0 -> consumer lane L = r0*4)
        {
            int mm = row & 63, wmw = row >> 6, mt = mm >> 4, r = mm & 15;
            int r0 = r & 7, rbit = r >> 3;
            int L = r0 << 2;
            int phys = L ^ (((L >> 3) & 3) << 1) ^ (ks & 1);
            int region = (ks * 2 + wmw) * 4 + mt;       // 0..31
            stA[i] = (uint32_t)(region * 512 + phys * 16 + khi * 8 + rbit * 4);
        }
        // B scatter base (component 0 -> consumer lane L = g*4)
        {
            int nn = row & 31, wnw = row >> 5, nt = nn >> 3, g = nn & 7;
            int np = nt >> 1, nb = nt & 1;
            int L = g << 2;
            int phys = L ^ (((L >> 3) & 3) << 1) ^ (ks & 1);
            int region = (ks * 4 + wnw) * 2 + np;       // 0..31
            stB[i] = (uint32_t)(B_REGION + region * 512 + phys * 16 + nb * 8 + khi * 4);
        }
    }

    const int lxs = lane ^ (((lane >> 3) & 3) << 1);

    float acc[4][4][4];
#pragma unroll
    for (int a = 0; a < 4; a++)
#pragma unroll
        for (int b = 0; b < 4; b++)
#pragma unroll
            for (int c = 0; c < 4; c++) acc[a][b][c] = 0.0f;

    uint4 vA[4], vB[4];

    // prologue: chunk 0
#pragma unroll
    for (int i = 0; i < 4; i++) {
        vA[i] = *(const uint4*)(gA[i]);
        vB[i] = *(const uint4*)(gB[i]);
    }
    {
        char* buf = smb;
#pragma unroll
        for (int i = 0; i < 4; i++) {
            // XOR scatter: toggles lane bits (addr bits 4..5) under the swizzle
            *(uint32_t*)(buf + (stA[i] ^ 0 )) = vA[i].x;
            *(uint32_t*)(buf + (stA[i] ^ 16)) = vA[i].y;
            *(uint32_t*)(buf + (stA[i] ^ 32)) = vA[i].z;
            *(uint32_t*)(buf + (stA[i] ^ 48)) = vA[i].w;
            *(uint32_t*)(buf + (stB[i] ^ 0 )) = vB[i].x;
            *(uint32_t*)(buf + (stB[i] ^ 16)) = vB[i].y;
            *(uint32_t*)(buf + (stB[i] ^ 32)) = vB[i].z;
            *(uint32_t*)(buf + (stB[i] ^ 48)) = vB[i].w;
        }
    }
    __syncthreads();

#pragma unroll 1
    for (int c = 0; c < NCH; c++) {
        if (c + 1 < NCH) {
            const int ko = (c + 1) * 64;
#pragma unroll
            for (int i = 0; i < 4; i++) {
                vA[i] = *(const uint4*)(gA[i] + ko);
                vB[i] = *(const uint4*)(gB[i] + ko);
            }
        }
        const char* buf = smb + (c & 1) * BUF_BYTES;
#pragma unroll
        for (int ks = 0; ks < 4; ks++) {
            const int lr = lxs ^ (ks & 1);
            uint4 afr[4], bfr[2];
#pragma unroll
            for (int mt = 0; mt < 4; mt++)
                afr[mt] = *(const uint4*)(buf + (((ks * 2 + wm) * 4 + mt) * 32 + lr) * 16);
#pragma unroll
            for (int np = 0; np < 2; np++)
                bfr[np] = *(const uint4*)(buf + B_REGION + (((ks * 4 + wn) * 2 + np) * 32 + lr) * 16);
#pragma unroll
            for (int mt = 0; mt < 4; mt++) {
                mma_f16(acc[mt][0], afr[mt], bfr[0].x, bfr[0].y);
                mma_f16(acc[mt][1], afr[mt], bfr[0].z, bfr[0].w);
                mma_f16(acc[mt][2], afr[mt], bfr[1].x, bfr[1].y);
                mma_f16(acc[mt][3], afr[mt], bfr[1].z, bfr[1].w);
            }
        }
        if (c + 1 < NCH) {
            char* nbuf = smb + ((c + 1) & 1) * BUF_BYTES;
#pragma unroll
            for (int i = 0; i < 4; i++) {
                *(uint32_t*)(nbuf + (stA[i] ^ 0 )) = vA[i].x;
                *(uint32_t*)(nbuf + (stA[i] ^ 16)) = vA[i].y;
                *(uint32_t*)(nbuf + (stA[i] ^ 32)) = vA[i].z;
                *(uint32_t*)(nbuf + (stA[i] ^ 48)) = vA[i].w;
                *(uint32_t*)(nbuf + (stB[i] ^ 0 )) = vB[i].x;
                *(uint32_t*)(nbuf + (stB[i] ^ 16)) = vB[i].y;
                *(uint32_t*)(nbuf + (stB[i] ^ 32)) = vB[i].z;
                *(uint32_t*)(nbuf + (stB[i] ^ 48)) = vB[i].w;
            }
        }
        __syncthreads();
    }

    // ---- epilogue: exp + row reduce + atomicAdd ----
    float s[4][2];
#pragma unroll
    for (int mt = 0; mt < 4; mt++) {
        float s0 = 0.0f, s1 = 0.0f;
#pragma unroll
        for (int nt = 0; nt < 4; nt++) {
            s0 += __expf(acc[mt][nt][0]) + __expf(acc[mt][nt][1]);
            s1 += __expf(acc[mt][nt][2]) + __expf(acc[mt][nt][3]);
        }
        s[mt][0] = s0; s[mt][1] = s1;
    }
#pragma unroll
    for (int o = 1; o < 4; o <<= 1)
#pragma unroll
        for (int mt = 0; mt < 4; mt++) {
            s[mt][0] += __shfl_xor_sync(0xffffffffu, s[mt][0], o);
            s[mt][1] += __shfl_xor_sync(0xffffffffu, s[mt][1], o);
        }
    if ((lane & 3) == 0) {
        int g = lane >> 2;
        int base = tm * BM + wm * 64 + g;
#pragma unroll
        for (int mt = 0; mt < 4; mt++) {
            atomicAdd(&g_rowsum[base + mt * 16],     s[mt][0]);
            atomicAdd(&g_rowsum[base + mt * 16 + 8], s[mt][1]);
        }
    }
}

// ---------------------------------------------------------------------------
__global__ void loss_kernel(float* __restrict__ out) {
    __shared__ double sh[1024];
    double a = 0.0;
    for (int b = threadIdx.x; b < B_ROWS; b += blockDim.x) {
        float t = fminf(fmaxf(g_tgt[b], -1.0f + EPS_CLIP), 1.0f - EPS_CLIP);
        float num = S_SCALE * cosf(acosf(t) + MARGIN);
        float excl = g_rowsum[b] - __expf(S_SCALE * t);
        double denom = (double)__expf(num) + (double)excl;
        a += (double)num - log(denom);
    }
    sh[threadIdx.x] = a;
    __syncthreads();
    for (int s = 512; s > 0; s >>= 1) {
        if (threadIdx.x < s) sh[threadIdx.x] += sh[threadIdx.x + s];
        __syncthreads();
    }
    if (threadIdx.x == 0) out[0] = (float)(-sh[0] / (double)B_ROWS);
}

// ---------------------------------------------------------------------------
extern "C" void kernel_launch(void* const* d_in, const int* in_sizes, int n_in,
                              void* d_out, int out_size) {
    const float* F = (const float*)d_in[0];
    const int*   Y = (const int*)d_in[1];
    const float* W = (const float*)d_in[2];
    float* out = (float*)d_out;

    cudaFuncSetAttribute(gemm_exp_mma_kernel,
                         cudaFuncAttributeMaxDynamicSharedMemorySize, 2 * BUF_BYTES);

    prep_kernel<<<PREP_BLOCKS, 256>>>(F, Y, W);

    dim3 grid(C_CLS / BN, B_ROWS / BM);   // (256, 16)
    gemm_exp_mma_kernel<<<grid, 256, 2 * BUF_BYTES>>>();

    loss_kernel<<<1, 1024>>>(out);
}

// round 7
// speedup vs baseline: 5.2181x; 1.0970x over previous
#include <cuda_runtime.h>
#include <cuda_fp16.h>
#include <math.h>
#include <stdint.h>

#define B_ROWS 2048
#define D_DIM  512
#define C_CLS  32768
#define S_SCALE 64.0f
#define SQRT_S 8.0f
#define MARGIN  0.5f
#define EPS_CLIP 1e-7f

#define BM 128
#define BN 128
#define NCH 4                  // 512 / 128 (k128 bytes per chunk)
#define BUF_BYTES 32768        // A 16KB + B 16KB per stage
#define B_REGION  16384

// prep grid split (8 warps = 8 rows per block)
#define PREP_W_BLOCKS  (C_CLS / 8)             // 4096
#define PREP_F_BLOCKS  (B_ROWS / 8)            // 256
#define PREP_T_BLOCKS  (B_ROWS / 8)            // 256
#define PREP_BLOCKS    (PREP_W_BLOCKS + PREP_F_BLOCKS + PREP_T_BLOCKS)

// ---------------------------------------------------------------------------
__device__ float  g_rowsum[B_ROWS];
__device__ float  g_tgt[B_ROWS];
__device__ __align__(16) uint8_t g_F8[B_ROWS * D_DIM];   // e4m3(8 * f_hat)
__device__ __align__(16) uint8_t g_W8[C_CLS * D_DIM];    // e4m3(8 * w_hat)

// fp8 e4m3 mma: D(16x8,f32) += A(16x32,e4m3) * B(8x32,e4m3)^T
__device__ __forceinline__ void mma_f8(float* c, const uint4& a,
                                       uint32_t b0, uint32_t b1) {
    asm volatile(
        "mma.sync.aligned.m16n8k32.row.col.f32.e4m3.e4m3.f32 "
        "{%0,%1,%2,%3}, {%4,%5,%6,%7}, {%8,%9}, {%0,%1,%2,%3};"
        : "+f"(c[0]), "+f"(c[1]), "+f"(c[2]), "+f"(c[3])
        : "r"(a.x), "r"(a.y), "r"(a.z), "r"(a.w), "r"(b0), "r"(b1));
}

// pack two floats -> 2 e4m3 bytes (lo -> low byte)
__device__ __forceinline__ uint32_t pack_e4m3x2(float lo, float hi) {
    uint16_t r;
    asm("cvt.rn.satfinite.e4m3x2.f32 %0, %1, %2;" : "=h"(r) : "f"(hi), "f"(lo));
    return (uint32_t)r;
}
__device__ __forceinline__ uint32_t pack_e4m3x4(float a, float b, float c, float d) {
    return pack_e4m3x2(a, b) | (pack_e4m3x2(c, d) << 16);
}

// ---------------------------------------------------------------------------
// Fused prep:
//   blocks [0, 4096)    : W rows -> g_W8 = e4m3(8 * w_hat)
//   blocks [4096, 4352) : F rows -> g_F8 = e4m3(8 * f_hat), zero g_rowsum
//   blocks [4352, 4608) : target cosine (exact fp32, self-contained)
__global__ void prep_kernel(const float* __restrict__ F,
                            const int* __restrict__ Y,
                            const float* __restrict__ W) {
    const int bid  = blockIdx.x;
    const int warp = threadIdx.x >> 5;
    const int lane = threadIdx.x & 31;

    if (bid < PREP_W_BLOCKS + PREP_F_BLOCKS) {
        const bool isW = bid < PREP_W_BLOCKS;
        int row = isW ? (bid * 8 + warp) : ((bid - PREP_W_BLOCKS) * 8 + warp);
        const float* src = isW ? W : F;
        if (!isW && lane == 0) g_rowsum[row] = 0.0f;
        const float4* p = (const float4*)(src + (size_t)row * D_DIM);
        float4 v[4]; float ss = 0.0f;
#pragma unroll
        for (int i = 0; i < 4; i++) {
            v[i] = p[lane + 32 * i];
            ss = fmaf(v[i].x, v[i].x, fmaf(v[i].y, v[i].y, fmaf(v[i].z, v[i].z, fmaf(v[i].w, v[i].w, ss))));
        }
#pragma unroll
        for (int o = 16; o; o >>= 1) ss += __shfl_xor_sync(0xffffffffu, ss, o);
        float sc = SQRT_S / fmaxf(sqrtf(ss), 1e-12f);
        uint8_t* dst = isW ? g_W8 : g_F8;
        // 16 floats -> 16 e4m3 bytes = one uint4 per thread per iteration group
        uint4 o4;
        o4.x = pack_e4m3x4(v[0].x * sc, v[0].y * sc, v[0].z * sc, v[0].w * sc);
        o4.y = pack_e4m3x4(v[1].x * sc, v[1].y * sc, v[1].z * sc, v[1].w * sc);
        o4.z = pack_e4m3x4(v[2].x * sc, v[2].y * sc, v[2].z * sc, v[2].w * sc);
        o4.w = pack_e4m3x4(v[3].x * sc, v[3].y * sc, v[3].z * sc, v[3].w * sc);
        // v[i] holds elements {lane+32i}*4 .. +3 ; byte addr must match element idx
        ((uint4*)(dst + (size_t)row * D_DIM))[lane] = make_uint4(0, 0, 0, 0); // placeholder overwritten below
        // NOTE: elements are strided: v[i] = elems [ (lane+32i)*4 .. +3 ]
        ((uint32_t*)(dst + (size_t)row * D_DIM))[lane +  0] = o4.x;
        ((uint32_t*)(dst + (size_t)row * D_DIM))[lane + 32] = o4.y;
        ((uint32_t*)(dst + (size_t)row * D_DIM))[lane + 64] = o4.z;
        ((uint32_t*)(dst + (size_t)row * D_DIM))[lane + 96] = o4.w;
    } else {
        int row = (bid - PREP_W_BLOCKS - PREP_F_BLOCKS) * 8 + warp;
        int cls = Y[row];
        const float4* fp = (const float4*)(F + (size_t)row * D_DIM);
        const float4* wp = (const float4*)(W + (size_t)cls * D_DIM);
        float dot = 0.0f, ff = 0.0f, ww = 0.0f;
#pragma unroll
        for (int i = 0; i < 4; i++) {
            float4 a = fp[lane + 32 * i];
            float4 b = wp[lane + 32 * i];
            dot = fmaf(a.x, b.x, fmaf(a.y, b.y, fmaf(a.z, b.z, fmaf(a.w, b.w, dot))));
            ff  = fmaf(a.x, a.x, fmaf(a.y, a.y, fmaf(a.z, a.z, fmaf(a.w, a.w, ff))));
            ww  = fmaf(b.x, b.x, fmaf(b.y, b.y, fmaf(b.z, b.z, fmaf(b.w, b.w, ww))));
        }
#pragma unroll
        for (int o = 16; o; o >>= 1) {
            dot += __shfl_xor_sync(0xffffffffu, dot, o);
            ff  += __shfl_xor_sync(0xffffffffu, ff,  o);
            ww  += __shfl_xor_sync(0xffffffffu, ww,  o);
        }
        if (lane == 0)
            g_tgt[row] = dot / (fmaxf(sqrtf(ff), 1e-12f) * fmaxf(sqrtf(ww), 1e-12f));
    }
}

// ---------------------------------------------------------------------------
// fp8 mma.sync m16n8k32 GEMM, 128x128 tile, K=512 in 4 chunks of 128 (bytes),
// double-buffered smem with fragment-ordered scatter stores (same layout as
// the fp16 version with k-granularity doubled; fragment reg shapes identical).
// acc = logit = 64 * cos. Epilogue: exp -> per-row sum -> atomicAdd.
__global__ void __launch_bounds__(256, 1)
gemm_exp_mma_kernel() {
    extern __shared__ __align__(16) char smb[];   // 2 * 32KB
    const int tid  = threadIdx.x;
    const int lane = tid & 31;
    const int warp = tid >> 5;
    const int wm = warp >> 2;          // 0..1   (m half)
    const int wn = warp & 3;           // 0..3   (n quarter)
    const int tm = blockIdx.y;
    const int tn = blockIdx.x;

    // ---- loader setup: per thread 4 LDG.128 of A + 4 of B per k128 chunk ----
    const uint8_t* gA[4];
    const uint8_t* gB[4];
    uint32_t stA[4], stB[4];   // smem byte offset of the component-0 slot
#pragma unroll
    for (int i = 0; i < 4; i++) {
        int idx = tid + i * 256;        // 0..1023
        int row = idx >> 3;             // 0..127
        int j   = idx & 7;              // 16-byte group in k128: k = j*16..j*16+15
        gA[i] = g_F8 + (size_t)(tm * BM + row) * D_DIM + j * 16;
        gB[i] = g_W8 + (size_t)(tn * BN + row) * D_DIM + j * 16;
        int ks  = j >> 1;               // k32 step 0..3
        int khi = j & 1;                // high k16 within the k32 step
        // A scatter base (component 0 -> consumer lane L = r0*4)
        {
            int mm = row & 63, wmw = row >> 6, mt = mm >> 4, r = mm & 15;
            int r0 = r & 7, rbit = r >> 3;
            int L = r0 << 2;
            int phys = L ^ (((L >> 3) & 3) << 1) ^ (ks & 1);
            int region = (ks * 2 + wmw) * 4 + mt;       // 0..31
            stA[i] = (uint32_t)(region * 512 + phys * 16 + khi * 8 + rbit * 4);
        }
        // B scatter base (component 0 -> consumer lane L = g*4)
        {
            int nn = row & 31, wnw = row >> 5, nt = nn >> 3, g = nn & 7;
            int np = nt >> 1, nb = nt & 1;
            int L = g << 2;
            int phys = L ^ (((L >> 3) & 3) << 1) ^ (ks & 1);
            int region = (ks * 4 + wnw) * 2 + np;       // 0..31
            stB[i] = (uint32_t)(B_REGION + region * 512 + phys * 16 + nb * 8 + khi * 4);
        }
    }

    const int lxs = lane ^ (((lane >> 3) & 3) << 1);

    float acc[4][4][4];
#pragma unroll
    for (int a = 0; a < 4; a++)
#pragma unroll
        for (int b = 0; b < 4; b++)
#pragma unroll
            for (int c = 0; c < 4; c++) acc[a][b][c] = 0.0f;

    uint4 vA[4], vB[4];

    // prologue: chunk 0
#pragma unroll
    for (int i = 0; i < 4; i++) {
        vA[i] = *(const uint4*)(gA[i]);
        vB[i] = *(const uint4*)(gB[i]);
    }
    {
        char* buf = smb;
#pragma unroll
        for (int i = 0; i < 4; i++) {
            // XOR scatter: toggles lane bits (addr bits 4..5) under the swizzle
            *(uint32_t*)(buf + (stA[i] ^ 0 )) = vA[i].x;
            *(uint32_t*)(buf + (stA[i] ^ 16)) = vA[i].y;
            *(uint32_t*)(buf + (stA[i] ^ 32)) = vA[i].z;
            *(uint32_t*)(buf + (stA[i] ^ 48)) = vA[i].w;
            *(uint32_t*)(buf + (stB[i] ^ 0 )) = vB[i].x;
            *(uint32_t*)(buf + (stB[i] ^ 16)) = vB[i].y;
            *(uint32_t*)(buf + (stB[i] ^ 32)) = vB[i].z;
            *(uint32_t*)(buf + (stB[i] ^ 48)) = vB[i].w;
        }
    }
    __syncthreads();

#pragma unroll 1
    for (int c = 0; c < NCH; c++) {
        if (c + 1 < NCH) {
            const int ko = (c + 1) * 128;
#pragma unroll
            for (int i = 0; i < 4; i++) {
                vA[i] = *(const uint4*)(gA[i] + ko);
                vB[i] = *(const uint4*)(gB[i] + ko);
            }
        }
        const char* buf = smb + (c & 1) * BUF_BYTES;
#pragma unroll
        for (int ks = 0; ks < 4; ks++) {
            const int lr = lxs ^ (ks & 1);
            uint4 afr[4], bfr[2];
#pragma unroll
            for (int mt = 0; mt < 4; mt++)
                afr[mt] = *(const uint4*)(buf + (((ks * 2 + wm) * 4 + mt) * 32 + lr) * 16);
#pragma unroll
            for (int np = 0; np < 2; np++)
                bfr[np] = *(const uint4*)(buf + B_REGION + (((ks * 4 + wn) * 2 + np) * 32 + lr) * 16);
#pragma unroll
            for (int mt = 0; mt < 4; mt++) {
                mma_f8(acc[mt][0], afr[mt], bfr[0].x, bfr[0].y);
                mma_f8(acc[mt][1], afr[mt], bfr[0].z, bfr[0].w);
                mma_f8(acc[mt][2], afr[mt], bfr[1].x, bfr[1].y);
                mma_f8(acc[mt][3], afr[mt], bfr[1].z, bfr[1].w);
            }
        }
        if (c + 1 < NCH) {
            char* nbuf = smb + ((c + 1) & 1) * BUF_BYTES;
#pragma unroll
            for (int i = 0; i < 4; i++) {
                *(uint32_t*)(nbuf + (stA[i] ^ 0 )) = vA[i].x;
                *(uint32_t*)(nbuf + (stA[i] ^ 16)) = vA[i].y;
                *(uint32_t*)(nbuf + (stA[i] ^ 32)) = vA[i].z;
                *(uint32_t*)(nbuf + (stA[i] ^ 48)) = vA[i].w;
                *(uint32_t*)(nbuf + (stB[i] ^ 0 )) = vB[i].x;
                *(uint32_t*)(nbuf + (stB[i] ^ 16)) = vB[i].y;
                *(uint32_t*)(nbuf + (stB[i] ^ 32)) = vB[i].z;
                *(uint32_t*)(nbuf + (stB[i] ^ 48)) = vB[i].w;
            }
        }
        __syncthreads();
    }

    // ---- epilogue: exp + row reduce + atomicAdd ----
    float s[4][2];
#pragma unroll
    for (int mt = 0; mt < 4; mt++) {
        float s0 = 0.0f, s1 = 0.0f;
#pragma unroll
        for (int nt = 0; nt < 4; nt++) {
            s0 += __expf(acc[mt][nt][0]) + __expf(acc[mt][nt][1]);
            s1 += __expf(acc[mt][nt][2]) + __expf(acc[mt][nt][3]);
        }
        s[mt][0] = s0; s[mt][1] = s1;
    }
#pragma unroll
    for (int o = 1; o < 4; o <<= 1)
#pragma unroll
        for (int mt = 0; mt < 4; mt++) {
            s[mt][0] += __shfl_xor_sync(0xffffffffu, s[mt][0], o);
            s[mt][1] += __shfl_xor_sync(0xffffffffu, s[mt][1], o);
        }
    if ((lane & 3) == 0) {
        int g = lane >> 2;
        int base = tm * BM + wm * 64 + g;
#pragma unroll
        for (int mt = 0; mt < 4; mt++) {
            atomicAdd(&g_rowsum[base + mt * 16],     s[mt][0]);
            atomicAdd(&g_rowsum[base + mt * 16 + 8], s[mt][1]);
        }
    }
}

// ---------------------------------------------------------------------------
__global__ void loss_kernel(float* __restrict__ out) {
    __shared__ double sh[1024];
    double a = 0.0;
    for (int b = threadIdx.x; b < B_ROWS; b += blockDim.x) {
        float t = fminf(fmaxf(g_tgt[b], -1.0f + EPS_CLIP), 1.0f - EPS_CLIP);
        float num = S_SCALE * cosf(acosf(t) + MARGIN);
        float excl = g_rowsum[b] - __expf(S_SCALE * t);
        double denom = (double)__expf(num) + (double)excl;
        a += (double)num - log(denom);
    }
    sh[threadIdx.x] = a;
    __syncthreads();
    for (int s = 512; s > 0; s >>= 1) {
        if (threadIdx.x < s) sh[threadIdx.x] += sh[threadIdx.x + s];
        __syncthreads();
    }
    if (threadIdx.x == 0) out[0] = (float)(-sh[0] / (double)B_ROWS);
}

// ---------------------------------------------------------------------------
extern "C" void kernel_launch(void* const* d_in, const int* in_sizes, int n_in,
                              void* d_out, int out_size) {
    const float* F = (const float*)d_in[0];
    const int*   Y = (const int*)d_in[1];
    const float* W = (const float*)d_in[2];
    float* out = (float*)d_out;

    cudaFuncSetAttribute(gemm_exp_mma_kernel,
                         cudaFuncAttributeMaxDynamicSharedMemorySize, 2 * BUF_BYTES);

    prep_kernel<<<PREP_BLOCKS, 256>>>(F, Y, W);

    dim3 grid(C_CLS / BN, B_ROWS / BM);   // (256, 16)
    gemm_exp_mma_kernel<<<grid, 256, 2 * BUF_BYTES>>>();

    loss_kernel<<<1, 1024>>>(out);
}